// round 1
// baseline (speedup 1.0000x reference)
#include <cuda_runtime.h>

// Comparator4Bit: A,B are (N,4) float32 with exact {0.0,1.0} entries.
// Column 0 = MSB (bit3) ... column 3 = LSB (bit0).
// Outputs: a_gt_b (N), a_eq_b (N), concatenated in d_out.
// Pure HBM-bound stream: 128 MiB in, 32 MiB out.

__global__ void __launch_bounds__(256)
comparator4_kernel(const float4* __restrict__ A,
                   const float4* __restrict__ B,
                   float* __restrict__ out_gt,
                   float* __restrict__ out_eq,
                   int n)
{
    int i = blockIdx.x * blockDim.x + threadIdx.x;
    if (i >= n) return;

    float4 a = A[i];
    float4 b = B[i];

    // x=bit3 (MSB), y=bit2, z=bit1, w=bit0
    bool e3 = (a.x == b.x);
    bool e2 = (a.y == b.y);
    bool e1 = (a.z == b.z);
    bool e0 = (a.w == b.w);
    bool g3 = (a.x > b.x);
    bool g2 = (a.y > b.y);
    bool g1 = (a.z > b.z);
    bool g0 = (a.w > b.w);

    // a_gt_b = g3 | e3&g2 | e3&e2&g1 | e3&e2&e1&g0  (Horner form)
    bool agtb = g3 | (e3 & (g2 | (e2 & (g1 | (e1 & g0)))));
    bool aeqb = e3 & e2 & e1 & e0;

    out_gt[i] = agtb ? 1.0f : 0.0f;
    out_eq[i] = aeqb ? 1.0f : 0.0f;
}

extern "C" void kernel_launch(void* const* d_in, const int* in_sizes, int n_in,
                              void* d_out, int out_size)
{
    const float4* A = (const float4*)d_in[0];
    const float4* B = (const float4*)d_in[1];

    int n = in_sizes[0] / 4;          // rows
    float* out = (float*)d_out;
    float* out_gt = out;              // first N floats
    float* out_eq = out + (out_size / 2);  // second N floats

    int threads = 256;
    int blocks = (n + threads - 1) / threads;
    comparator4_kernel<<<blocks, threads>>>(A, B, out_gt, out_eq, n);
}

// round 3
// speedup vs baseline: 1.1737x; 1.1737x over previous
#include <cuda_runtime.h>

// Comparator4Bit: A,B are (N,4) float32 with exact {0.0,1.0} entries.
// Column 0 = MSB (bit3) ... column 3 = LSB (bit0).
// Outputs: a_gt_b (N) | a_eq_b (N) concatenated in d_out.
//
// R2: 4 rows per thread -> 8 front-batched LDG.128 (MLP_p1=8) and
// vectorized STG.128 outputs; streaming cache hints (__ldcs/__stcs)
// since every byte is touched exactly once.

__global__ void __launch_bounds__(256)
comparator4_kernel(const float4* __restrict__ A,
                   const float4* __restrict__ B,
                   float4* __restrict__ out_gt,   // one float4 = 4 rows' gt results
                   float4* __restrict__ out_eq,
                   int nquad)                     // nquad = N/4
{
    int q = blockIdx.x * blockDim.x + threadIdx.x;
    if (q >= nquad) return;

    const float4* Ap = A + 4 * (size_t)q;
    const float4* Bp = B + 4 * (size_t)q;

    // Front-batch all 8 loads so they issue back-to-back (deep MLP).
    float4 a0 = __ldcs(Ap + 0);
    float4 a1 = __ldcs(Ap + 1);
    float4 a2 = __ldcs(Ap + 2);
    float4 a3 = __ldcs(Ap + 3);
    float4 b0 = __ldcs(Bp + 0);
    float4 b1 = __ldcs(Bp + 1);
    float4 b2 = __ldcs(Bp + 2);
    float4 b3 = __ldcs(Bp + 3);

    float gt[4], eq[4];

    float4 av[4] = {a0, a1, a2, a3};
    float4 bv[4] = {b0, b1, b2, b3};

#pragma unroll
    for (int r = 0; r < 4; r++) {
        float4 a = av[r];
        float4 b = bv[r];
        // x=bit3 (MSB), y=bit2, z=bit1, w=bit0
        bool e3 = (a.x == b.x);
        bool e2 = (a.y == b.y);
        bool e1 = (a.z == b.z);
        bool e0 = (a.w == b.w);
        bool g3 = (a.x > b.x);
        bool g2 = (a.y > b.y);
        bool g1 = (a.z > b.z);
        bool g0 = (a.w > b.w);

        bool agtb = g3 | (e3 & (g2 | (e2 & (g1 | (e1 & g0)))));
        bool aeqb = e3 & e2 & e1 & e0;

        gt[r] = agtb ? 1.0f : 0.0f;
        eq[r] = aeqb ? 1.0f : 0.0f;
    }

    float4 gto = make_float4(gt[0], gt[1], gt[2], gt[3]);
    float4 eqo = make_float4(eq[0], eq[1], eq[2], eq[3]);
    __stcs(out_gt + q, gto);
    __stcs(out_eq + q, eqo);
}

extern "C" void kernel_launch(void* const* d_in, const int* in_sizes, int n_in,
                              void* d_out, int out_size)
{
    const float4* A = (const float4*)d_in[0];
    const float4* B = (const float4*)d_in[1];

    int n = in_sizes[0] / 4;          // rows (N)
    int nquad = n / 4;                // 4 rows per thread (N = 4194304 divisible)

    float* out = (float*)d_out;
    float4* out_gt = (float4*)out;                     // first N floats
    float4* out_eq = (float4*)(out + (out_size / 2));  // second N floats

    int threads = 256;
    int blocks = (nquad + threads - 1) / threads;
    comparator4_kernel<<<blocks, threads>>>(A, B, out_gt, out_eq, nquad);
}

// round 6
// speedup vs baseline: 1.2013x; 1.0235x over previous
#include <cuda_runtime.h>

// Comparator4Bit: A,B are (N,4) float32 with exact {0.0,1.0} entries.
// Column 0 = MSB (bit3) ... column 3 = LSB (bit0).
// Outputs: a_gt_b (N) | a_eq_b (N) concatenated in d_out.
//
// R4: 4 rows/thread with WARP-COALESCED per-instruction access:
// thread t handles rows base + t + k*256 (k=0..3), so every LDG.128 /
// STG.32 has consecutive lanes (4 lines per 128-byte request), while
// keeping 8 front-batched loads in flight (MLP_p1 = 8).

#define TPB 256
#define ROWS_PER_THREAD 4

__global__ void __launch_bounds__(TPB)
comparator4_kernel(const float4* __restrict__ A,
                   const float4* __restrict__ B,
                   float* __restrict__ out_gt,
                   float* __restrict__ out_eq,
                   int n)   // total rows
{
    int base = blockIdx.x * (TPB * ROWS_PER_THREAD) + threadIdx.x;

    // N = 4194304 = 4096 blocks * 1024 rows/block exactly; guard anyway.
    if (base + 3 * TPB >= n) {
        for (int k = 0; k < ROWS_PER_THREAD; k++) {
            int i = base + k * TPB;
            if (i < n) {
                float4 a = __ldcs(A + i);
                float4 b = __ldcs(B + i);
                bool e3 = (a.x == b.x), e2 = (a.y == b.y);
                bool e1 = (a.z == b.z), e0 = (a.w == b.w);
                bool g3 = (a.x > b.x), g2 = (a.y > b.y);
                bool g1 = (a.z > b.z), g0 = (a.w > b.w);
                bool agtb = g3 | (e3 & (g2 | (e2 & (g1 | (e1 & g0)))));
                bool aeqb = e3 & e2 & e1 & e0;
                out_gt[i] = agtb ? 1.0f : 0.0f;
                out_eq[i] = aeqb ? 1.0f : 0.0f;
            }
        }
        return;
    }

    // Fast path: front-batch all 8 coalesced LDG.128s.
    float4 a0 = __ldcs(A + base + 0 * TPB);
    float4 a1 = __ldcs(A + base + 1 * TPB);
    float4 a2 = __ldcs(A + base + 2 * TPB);
    float4 a3 = __ldcs(A + base + 3 * TPB);
    float4 b0 = __ldcs(B + base + 0 * TPB);
    float4 b1 = __ldcs(B + base + 1 * TPB);
    float4 b2 = __ldcs(B + base + 2 * TPB);
    float4 b3 = __ldcs(B + base + 3 * TPB);

    float4 av[ROWS_PER_THREAD] = {a0, a1, a2, a3};
    float4 bv[ROWS_PER_THREAD] = {b0, b1, b2, b3};
    float gt[ROWS_PER_THREAD], eq[ROWS_PER_THREAD];

#pragma unroll
    for (int k = 0; k < ROWS_PER_THREAD; k++) {
        float4 a = av[k];
        float4 b = bv[k];
        // x=bit3 (MSB), y=bit2, z=bit1, w=bit0
        bool e3 = (a.x == b.x), e2 = (a.y == b.y);
        bool e1 = (a.z == b.z), e0 = (a.w == b.w);
        bool g3 = (a.x > b.x), g2 = (a.y > b.y);
        bool g1 = (a.z > b.z), g0 = (a.w > b.w);
        bool agtb = g3 | (e3 & (g2 | (e2 & (g1 | (e1 & g0)))));
        bool aeqb = e3 & e2 & e1 & e0;
        gt[k] = agtb ? 1.0f : 0.0f;
        eq[k] = aeqb ? 1.0f : 0.0f;
    }

#pragma unroll
    for (int k = 0; k < ROWS_PER_THREAD; k++) {
        __stcs(out_gt + base + k * TPB, gt[k]);
        __stcs(out_eq + base + k * TPB, eq[k]);
    }
}

extern "C" void kernel_launch(void* const* d_in, const int* in_sizes, int n_in,
                              void* d_out, int out_size)
{
    const float4* A = (const float4*)d_in[0];
    const float4* B = (const float4*)d_in[1];

    int n = in_sizes[0] / 4;          // rows (N)
    float* out = (float*)d_out;
    float* out_gt = out;                    // first N floats
    float* out_eq = out + (out_size / 2);   // second N floats

    int rows_per_block = TPB * ROWS_PER_THREAD;
    int blocks = (n + rows_per_block - 1) / rows_per_block;
    comparator4_kernel<<<blocks, TPB>>>(A, B, out_gt, out_eq, n);
}